// round 8
// baseline (speedup 1.0000x reference)
#include <cuda_runtime.h>
#include <cuda_fp16.h>
#include <stdint.h>

#define NH 3
#define NB 16
#define NN 1024
#define NF 512
#define NFP 1024

// ---------------------------------------------------------------------------
// Scratch arena
// ---------------------------------------------------------------------------
#define OFF_XH    0ull            // x fp16 [b][n][f]             16 MB
#define OFF_KTH   16777216ull     // kernels^T fp16 [h][fp][f]     3 MB
#define OFF_FTH   19922944ull     // feats fp16 [hb][node][fp]    96 MB
#define OFF_S1    120586240ull    // suffix sums fp32 [hb][idx][fp] 192 MB
#define OFF_S2    321912832ull    // prefix sums fp32 [hb][idx][fp] 192 MB
#define OFF_CS    523239424ull    // sorted c fp32 [hb][idx]
#define OFF_PERM  523436032ull    // perm int [hb][idx]
#define OFF_W1    523632640ull    // e^{c-M} [hb][idx]
#define OFF_W2    523829248ull    // e^{0.2(c-M)} [hb][idx]
#define OFF_Z1S   524025856ull    // scalar suffix sums
#define OFF_Z2P   524222464ull    // scalar prefix sums
#define OFF_M1    524419072ull    // per-hb max c (48 floats)
#define OFF_W2S   524419328ull
#define OFF_W2N   524425472ull
#define OFF_SS    524431616ull
#define OFF_SN    524628224ull
#define OFF_BM    524824832ull
#define ARENA_SZ  524828928ull

__device__ __align__(128) unsigned char g_arena[ARENA_SZ];
#define AP(T, off) ((T*)(g_arena + (off)))

// ---------------------------------------------------------------------------
// PTX helpers (base sm_103 target)
// ---------------------------------------------------------------------------
__device__ __forceinline__ uint32_t smem_u32(const void* p) {
    uint32_t a;
    asm("{ .reg .u64 t; cvta.to.shared.u64 t, %1; cvt.u32.u64 %0, t; }"
        : "=r"(a) : "l"(p));
    return a;
}
__device__ __forceinline__ void cpasync16(uint32_t s, const void* g) {
    asm volatile("cp.async.cg.shared.global [%0], [%1], 16;"
                 :: "r"(s), "l"(g) : "memory");
}
__device__ __forceinline__ void cp_commit() {
    asm volatile("cp.async.commit_group;" ::: "memory");
}
template <int N>
__device__ __forceinline__ void cp_wait() {
    asm volatile("cp.async.wait_group %0;" :: "n"(N) : "memory");
}
__device__ __forceinline__ void ldsm4(uint32_t* r, uint32_t a) {
    asm volatile("ldmatrix.sync.aligned.m8n8.x4.shared.b16 {%0,%1,%2,%3}, [%4];"
                 : "=r"(r[0]), "=r"(r[1]), "=r"(r[2]), "=r"(r[3]) : "r"(a));
}
__device__ __forceinline__ void mma16816(float* c, const uint32_t* a,
                                         const uint32_t* b) {
    asm volatile(
        "mma.sync.aligned.m16n8k16.row.col.f32.f16.f16.f32 "
        "{%0,%1,%2,%3}, {%4,%5,%6,%7}, {%8,%9}, {%0,%1,%2,%3};"
        : "+f"(c[0]), "+f"(c[1]), "+f"(c[2]), "+f"(c[3])
        : "r"(a[0]), "r"(a[1]), "r"(a[2]), "r"(a[3]), "r"(b[0]), "r"(b[1]));
}

// ---------------------------------------------------------------------------
// GEMM core (R5 config): 128x128 CTA tile, kc=64, fp16 K-major, 2 CTAs/SM.
// ---------------------------------------------------------------------------
#define GP_PITCH  144
#define G_TILE    18432
#define G_STAGE   36864
#define G_SMEM    110592

__device__ __forceinline__ void ld_stage(
    uint32_t st, int tid, const __half* A, const __half* B, int lda, int ldb)
{
#pragma unroll
    for (int it = 0; it < 4; it++) {
        const int idx = it * 256 + tid;
        const int row = idx >> 3, seg = idx & 7;
        const uint32_t so = row * GP_PITCH + seg * 16;
        cpasync16(st + so,          (const char*)(A + (size_t)row * lda) + seg * 16);
        cpasync16(st + G_TILE + so, (const char*)(B + (size_t)row * ldb) + seg * 16);
    }
    cp_commit();
}

template <int S, int KPH>
__device__ __forceinline__ void gemm_mma(
    const __half* A0, const __half* B0, size_t hst, int lda, int ldb,
    uint32_t sb, float acc[4][4][4], int wm, int wn, int lane, int tid)
{
#pragma unroll
    for (int mt = 0; mt < 4; mt++)
#pragma unroll
        for (int nt = 0; nt < 4; nt++)
#pragma unroll
            for (int q = 0; q < 4; q++) acc[mt][nt][q] = 0.f;

    ld_stage(sb,           tid, A0,      B0,      lda, ldb);
    ld_stage(sb + G_STAGE, tid, A0 + 64, B0 + 64, lda, ldb);

    for (int s = 0; s < S; s++) {
        if (s < S - 1) cp_wait<1>(); else cp_wait<0>();
        __syncthreads();
        const int sn = s + 2;
        if (sn < S) {
            const int hh = sn / KPH, kt = (sn % KPH) * 64;
            ld_stage(sb + (sn % 3) * G_STAGE, tid,
                     A0 + hh * hst + kt, B0 + hh * hst + kt, lda, ldb);
        }
        const uint32_t bu = sb + (s % 3) * G_STAGE;
        const uint32_t Ab = bu, Bb = bu + G_TILE;
#pragma unroll
        for (int ks = 0; ks < 4; ks++) {
            uint32_t bq[4][2];
            const int bcol = ks * 16 + (((lane >> 3) & 1) << 3);
            const int brow_in = ((lane >> 4) << 3) + (lane & 7);
#pragma unroll
            for (int p = 0; p < 2; p++) {
                uint32_t r[4];
                const int brow = wn * 32 + p * 16 + brow_in;
                ldsm4(r, Bb + (uint32_t)brow * GP_PITCH + bcol * 2);
                bq[2 * p][0] = r[0]; bq[2 * p][1] = r[1];
                bq[2 * p + 1][0] = r[2]; bq[2 * p + 1][1] = r[3];
            }
            const int arow = wm * 64 + (lane & 15);
            const int acol = ks * 16 + (lane >> 4) * 8;
#pragma unroll
            for (int mt = 0; mt < 4; mt++) {
                uint32_t aq[4];
                ldsm4(aq, Ab + (uint32_t)(arow + mt * 16) * GP_PITCH + acol * 2);
#pragma unroll
                for (int nt = 0; nt < 4; nt++)
                    mma16816(acc[mt][nt], aq, bq[nt]);
            }
        }
    }
}

// ---------------------------------------------------------------------------
// feats GEMM: feats[hb][node][fp] = sum_f x[b][node][f] * kT[h][fp][f]
// M = node, N = fp. Output row-major [node][fp] (fp contiguous).
// ---------------------------------------------------------------------------
__global__ void __launch_bounds__(256, 2) feats_tc() {
    extern __shared__ char dynsm[];
    const int tid = threadIdx.x;
    const int w = tid >> 5, lane = tid & 31;
    const int wm = w & 1, wn = w >> 1;
    const int z = blockIdx.z, h = z >> 4, b = z & 15;
    const int m0 = blockIdx.y * 128;   // node tile
    const int n0 = blockIdx.x * 128;   // fp tile

    const __half* A0 = AP(__half, OFF_XH)  + (size_t)b * NN * NF + (size_t)m0 * NF;
    const __half* B0 = AP(__half, OFF_KTH) + (size_t)h * NFP * NF + (size_t)n0 * NF;

    float acc[4][4][4];
    gemm_mma<8, 8>(A0, B0, 0, NF, NF, smem_u32(dynsm), acc, wm, wn, lane, tid);

    __half* ft = AP(__half, OFF_FTH) + (size_t)z * NN * NFP;
#pragma unroll
    for (int mt = 0; mt < 4; mt++)
#pragma unroll
        for (int nt = 0; nt < 4; nt++)
#pragma unroll
            for (int hf = 0; hf < 2; hf++) {
                const int row = m0 + wm * 64 + mt * 16 + (lane >> 2) + hf * 8;
                const int col = n0 + wn * 32 + nt * 8 + (lane & 3) * 2;
                __half2 p;
                p.x = __float2half(acc[mt][nt][hf * 2 + 0]);
                p.y = __float2half(acc[mt][nt][hf * 2 + 1]);
                *(__half2*)(ft + (size_t)row * NFP + col) = p;
            }
}

// ---------------------------------------------------------------------------
// Prep kernels
// ---------------------------------------------------------------------------
__global__ void prep_x(const float* __restrict__ x) {
    const size_t i = (size_t)blockIdx.x * 256 + threadIdx.x;
    float4 v = ((const float4*)x)[i];
    union { __half h[4]; uint2 u; } o;
    o.h[0] = __float2half(v.x); o.h[1] = __float2half(v.y);
    o.h[2] = __float2half(v.z); o.h[3] = __float2half(v.w);
    ((uint2*)AP(unsigned char, OFF_XH))[i] = o.u;
}

__global__ void prep_kT(const float* __restrict__ kern) {
    __shared__ float t[32][33];
    const int h = blockIdx.z;
    const int fp0 = blockIdx.x * 32, f0 = blockIdx.y * 32;
    const float* src = kern + (size_t)h * NF * NFP;
#pragma unroll
    for (int j = 0; j < 4; j++)
        t[threadIdx.y + j * 8][threadIdx.x] =
            src[(size_t)(f0 + threadIdx.y + j * 8) * NFP + fp0 + threadIdx.x];
    __syncthreads();
    __half* dst = AP(__half, OFF_KTH) + (size_t)h * NFP * NF;
#pragma unroll
    for (int j = 0; j < 4; j++) {
        float v = t[threadIdx.x][threadIdx.y + j * 8];
        dst[(size_t)(fp0 + threadIdx.y + j * 8) * NF + f0 + threadIdx.x] =
            __float2half(v);
    }
}

__global__ void w2k(const float* __restrict__ kern,
                    const float* __restrict__ as, const float* __restrict__ an) {
    const int gw = blockIdx.x * 8 + (threadIdx.x >> 5);
    const int lane = threadIdx.x & 31;
    const int h = gw >> 9, f = gw & 511;
    const float* row = kern + ((size_t)h * NF + f) * NFP;
    const float* a1 = as + (size_t)h * NFP;
    const float* a2 = an + (size_t)h * NFP;
    float s1 = 0.f, s2 = 0.f;
#pragma unroll
    for (int it = 0; it < 8; it++) {
        int k = it * 128 + lane * 4;
        float4 kv = *(const float4*)(row + k);
        float4 v1 = *(const float4*)(a1 + k);
        float4 v2 = *(const float4*)(a2 + k);
        s1 += kv.x * v1.x + kv.y * v1.y + kv.z * v1.z + kv.w * v1.w;
        s2 += kv.x * v2.x + kv.y * v2.y + kv.z * v2.z + kv.w * v2.w;
    }
#pragma unroll
    for (int o = 16; o > 0; o >>= 1) {
        s1 += __shfl_xor_sync(0xFFFFFFFFu, s1, o);
        s2 += __shfl_xor_sync(0xFFFFFFFFu, s2, o);
    }
    if (lane == 0) {
        AP(float, OFF_W2S)[(size_t)h * NF + f] = s1;
        AP(float, OFF_W2N)[(size_t)h * NF + f] = s2;
    }
}

__global__ void __launch_bounds__(256) s_comp(const float* __restrict__ x) {
    __shared__ float ws[NH * NF], wn_[NH * NF];
    for (int i = threadIdx.x; i < NH * NF; i += 256) {
        ws[i]  = AP(float, OFF_W2S)[i];
        wn_[i] = AP(float, OFF_W2N)[i];
    }
    __syncthreads();
    const int gw = blockIdx.x * 8 + (threadIdx.x >> 5);
    const int lane = threadIdx.x & 31;
    const int b = gw >> 10, n = gw & 1023;
    const float* xr = x + ((size_t)b * NN + n) * NF;
    float a[3] = {0.f, 0.f, 0.f}, c[3] = {0.f, 0.f, 0.f};
#pragma unroll
    for (int it = 0; it < 4; it++) {
        int f = it * 128 + lane * 4;
        float4 xv = *(const float4*)(xr + f);
#pragma unroll
        for (int h = 0; h < 3; h++) {
            float4 w = *(const float4*)&ws[h * NF + f];
            float4 u = *(const float4*)&wn_[h * NF + f];
            a[h] += xv.x * w.x + xv.y * w.y + xv.z * w.z + xv.w * w.w;
            c[h] += xv.x * u.x + xv.y * u.y + xv.z * u.z + xv.w * u.w;
        }
    }
#pragma unroll
    for (int h = 0; h < 3; h++) {
#pragma unroll
        for (int o = 16; o > 0; o >>= 1) {
            a[h] += __shfl_xor_sync(0xFFFFFFFFu, a[h], o);
            c[h] += __shfl_xor_sync(0xFFFFFFFFu, c[h], o);
        }
    }
    if (lane == 0) {
#pragma unroll
        for (int h = 0; h < 3; h++) {
            AP(float, OFF_SS)[(size_t)h * NB * NN + b * NN + n] = a[h];
            AP(float, OFF_SN)[(size_t)h * NB * NN + b * NN + n] = c[h];
        }
    }
}

// Row softmax (exact, fp32) -> d_out attn slices. No fp16 copy anymore.
__global__ void __launch_bounds__(256) attn_softmax(float* __restrict__ out) {
    __shared__ float c[NN];
    const int w    = threadIdx.x >> 5;
    const int lane = threadIdx.x & 31;
    const size_t r0 = (size_t)blockIdx.x * 8;
    const size_t hb = r0 >> 10;
    const float* cn = AP(float, OFF_SN) + hb * NN;
    for (int i = threadIdx.x; i < NN; i += 256) c[i] = cn[i];
    __syncthreads();

    const size_t r = r0 + w;
    const float a = AP(float, OFF_SS)[r];

    float ev[32];
    float m = -1e30f;
#pragma unroll
    for (int it = 0; it < 32; it++) {
        float t = a + c[it * 32 + lane];
        t = (t >= 0.f) ? t : 0.2f * t;
        ev[it] = t;
        m = fmaxf(m, t);
    }
#pragma unroll
    for (int o = 16; o > 0; o >>= 1) m = fmaxf(m, __shfl_xor_sync(0xFFFFFFFFu, m, o));
    float s = 0.f;
#pragma unroll
    for (int it = 0; it < 32; it++) {
        float e = __expf(ev[it] - m);
        ev[it] = e;
        s += e;
    }
#pragma unroll
    for (int o = 16; o > 0; o >>= 1) s += __shfl_xor_sync(0xFFFFFFFFu, s, o);
    const float inv = 1.f / s;

    float* orow = out + r * NN;
#pragma unroll
    for (int it = 0; it < 32; it++)
        orow[it * 32 + lane] = ev[it] * inv;
}

__global__ void bias_mean(const float* __restrict__ biases) {
    int k = blockIdx.x * 256 + threadIdx.x;
    AP(float, OFF_BM)[k] =
        (biases[k] + biases[NFP + k] + biases[2 * NFP + k]) * (1.f / 3.f);
}

// ---------------------------------------------------------------------------
// Sort c ascending per (h,b): bitonic in smem; emit perm, csort, weights and
// scalar prefix/suffix sums.
// ---------------------------------------------------------------------------
__global__ void __launch_bounds__(1024) void_dummy();  // (unused decl guard)

__global__ void __launch_bounds__(1024) sort_c() {
    __shared__ float key[1024];
    __shared__ int   val[1024];
    __shared__ float buf[1024];
    const int hb = blockIdx.x, tid = threadIdx.x;
    key[tid] = AP(float, OFF_SN)[(size_t)hb * NN + tid];
    val[tid] = tid;
    __syncthreads();
    for (int ksz = 2; ksz <= 1024; ksz <<= 1)
        for (int j = ksz >> 1; j > 0; j >>= 1) {
            const int ixj = tid ^ j;
            if (ixj > tid) {
                const bool asc = ((tid & ksz) == 0);
                float a = key[tid], bb = key[ixj];
                if ((a > bb) == asc) {
                    key[tid] = bb; key[ixj] = a;
                    int tv = val[tid]; val[tid] = val[ixj]; val[ixj] = tv;
                }
            }
            __syncthreads();
        }
    const float M1 = key[1023];
    const float cv = key[tid];
    const float w1 = __expf(cv - M1);
    const float w2 = __expf(0.2f * (cv - M1));
    AP(float, OFF_CS)[(size_t)hb * NN + tid] = cv;
    AP(int,   OFF_PERM)[(size_t)hb * NN + tid] = val[tid];
    AP(float, OFF_W1)[(size_t)hb * NN + tid] = w1;
    AP(float, OFF_W2)[(size_t)hb * NN + tid] = w2;
    if (tid == 0) AP(float, OFF_M1)[hb] = M1;
    __syncthreads();

    // z2pre: inclusive forward scan of w2
    buf[tid] = w2;
    __syncthreads();
    for (int off = 1; off < 1024; off <<= 1) {
        float v = (tid >= off) ? buf[tid - off] : 0.f;
        __syncthreads();
        buf[tid] += v;
        __syncthreads();
    }
    AP(float, OFF_Z2P)[(size_t)hb * NN + tid] = buf[tid];
    __syncthreads();

    // z1suf: inclusive scan of reversed w1
    buf[1023 - tid] = w1;
    __syncthreads();
    for (int off = 1; off < 1024; off <<= 1) {
        float v = (tid >= off) ? buf[tid - off] : 0.f;
        __syncthreads();
        buf[tid] += v;
        __syncthreads();
    }
    AP(float, OFF_Z1S)[(size_t)hb * NN + (1023 - tid)] = buf[tid];
}

// ---------------------------------------------------------------------------
// Vector scans: S1[idx][fp] = sum_{t>=idx} w1[t]*feats[perm[t]][fp]  (Kahan)
//               S2[idx][fp] = sum_{t<=idx} w2[t]*feats[perm[t]][fp]
// grid 96: (hb, half of fp range), 512 threads.
// ---------------------------------------------------------------------------
__global__ void __launch_bounds__(512) scan_feats() {
    __shared__ int   sp[1024];
    __shared__ float sw1[1024], sw2[1024];
    const int hb = blockIdx.x >> 1;
    const int fp = ((blockIdx.x & 1) << 9) + threadIdx.x;
    for (int i = threadIdx.x; i < 1024; i += 512) {
        sp[i]  = AP(int,   OFF_PERM)[(size_t)hb * NN + i];
        sw1[i] = AP(float, OFF_W1)[(size_t)hb * NN + i];
        sw2[i] = AP(float, OFF_W2)[(size_t)hb * NN + i];
    }
    __syncthreads();
    const __half* ft = AP(__half, OFF_FTH) + (size_t)hb * NN * NFP;
    float* S1 = AP(float, OFF_S1) + (size_t)hb * NN * NFP;
    float* S2 = AP(float, OFF_S2) + (size_t)hb * NN * NFP;

    float acc = 0.f, comp = 0.f;
    for (int idx = 1023; idx >= 0; --idx) {
        float f = __half2float(ft[(size_t)sp[idx] * NFP + fp]);
        float y = fmaf(sw1[idx], f, -comp);
        float t = acc + y;
        comp = (t - acc) - y;
        acc = t;
        S1[(size_t)idx * NFP + fp] = acc;
    }
    acc = 0.f; comp = 0.f;
    for (int idx = 0; idx < 1024; ++idx) {
        float f = __half2float(ft[(size_t)sp[idx] * NFP + fp]);
        float y = fmaf(sw2[idx], f, -comp);
        float t = acc + y;
        comp = (t - acc) - y;
        acc = t;
        S2[(size_t)idx * NFP + fp] = acc;
    }
}

// ---------------------------------------------------------------------------
// Combine: out[b][i][:] = (1/3) sum_h (S1[k]+q*S2[k-1]) / (z1[k]+q*z2[k-1]) + bm
// One CTA per (b,i), 256 threads x float4.
// ---------------------------------------------------------------------------
__global__ void __launch_bounds__(256) combine(float* __restrict__ out) {
    const int bi = blockIdx.x;
    const int b = bi >> 10, i = bi & 1023;
    __shared__ int   sk[3];
    __shared__ float sq[3], siz[3];
    if (threadIdx.x < 3) {
        const int h = threadIdx.x, hb = h * NB + b;
        const float s = AP(float, OFF_SS)[(size_t)hb * NN + i];
        const float* cs = AP(float, OFF_CS) + (size_t)hb * NN;
        int lo = 0, hi = 1024;
        while (lo < hi) {
            int mid = (lo + hi) >> 1;
            if (s + cs[mid] >= 0.f) hi = mid; else lo = mid + 1;
        }
        const float q = __expf(-0.8f * (s + AP(float, OFF_M1)[hb]));
        const float z1 = (lo < 1024) ? AP(float, OFF_Z1S)[(size_t)hb * NN + lo] : 0.f;
        const float z2 = (lo > 0) ? AP(float, OFF_Z2P)[(size_t)hb * NN + lo - 1] : 0.f;
        sk[h] = lo; sq[h] = q; siz[h] = 1.f / (z1 + q * z2);
    }
    __syncthreads();
    const int fp = threadIdx.x * 4;
    float ox = 0.f, oy = 0.f, oz = 0.f, ow = 0.f;
#pragma unroll
    for (int h = 0; h < 3; h++) {
        const int hb = h * NB + b, k = sk[h];
        const float q = sq[h], iz = siz[h];
        float4 a1 = make_float4(0.f, 0.f, 0.f, 0.f);
        float4 a2 = make_float4(0.f, 0.f, 0.f, 0.f);
        if (k < 1024)
            a1 = *(const float4*)(AP(float, OFF_S1) + ((size_t)hb * NN + k) * NFP + fp);
        if (k > 0)
            a2 = *(const float4*)(AP(float, OFF_S2) + ((size_t)hb * NN + k - 1) * NFP + fp);
        ox += (a1.x + q * a2.x) * iz;
        oy += (a1.y + q * a2.y) * iz;
        oz += (a1.z + q * a2.z) * iz;
        ow += (a1.w + q * a2.w) * iz;
    }
    const float* bm = AP(float, OFF_BM);
    float4 r;
    r.x = ox * (1.f / 3.f) + bm[fp + 0];
    r.y = oy * (1.f / 3.f) + bm[fp + 1];
    r.z = oz * (1.f / 3.f) + bm[fp + 2];
    r.w = ow * (1.f / 3.f) + bm[fp + 3];
    *(float4*)(out + ((size_t)(NH * NB) + b) * NN * NN + (size_t)i * NN + fp) = r;
}

// ---------------------------------------------------------------------------
extern "C" void kernel_launch(void* const* d_in, const int* in_sizes, int n_in,
                              void* d_out, int out_size)
{
    const float* x      = (const float*)d_in[0];
    const float* kern   = (const float*)d_in[1];
    const float* biases = (const float*)d_in[2];
    const float* aself  = (const float*)d_in[3];
    const float* aneigh = (const float*)d_in[4];
    float* out = (float*)d_out;

    static cudaStream_t s1 = nullptr;
    static cudaEvent_t efork = nullptr, esort = nullptr, eside = nullptr;
    static bool attr_done = false;
    if (s1 == nullptr) {
        cudaStreamCreateWithFlags(&s1, cudaStreamNonBlocking);
        cudaEventCreateWithFlags(&efork, cudaEventDisableTiming);
        cudaEventCreateWithFlags(&esort, cudaEventDisableTiming);
        cudaEventCreateWithFlags(&eside, cudaEventDisableTiming);
    }
    if (!attr_done) {
        cudaFuncSetAttribute(feats_tc, cudaFuncAttributeMaxDynamicSharedMemorySize, G_SMEM);
        attr_done = true;
    }

    // Fork
    cudaEventRecord(efork, 0);
    cudaStreamWaitEvent(s1, efork, 0);

    // Side stream: logits chain, sort, softmax, bias
    w2k<<<(NH * NF) / 8, 256, 0, s1>>>(kern, aself, aneigh);
    s_comp<<<(NB * NN) / 8, 256, 0, s1>>>(x);
    sort_c<<<NH * NB, 1024, 0, s1>>>();
    cudaEventRecord(esort, s1);
    attn_softmax<<<(NH * NB * NN) / 8, 256, 0, s1>>>(out);
    bias_mean<<<NFP / 256, 256, 0, s1>>>(biases);
    cudaEventRecord(eside, s1);

    // Main stream: fp16 prep + feats GEMM
    prep_x<<<(NB * NN * NF / 4) / 256, 256>>>(x);
    prep_kT<<<dim3(NFP / 32, NF / 32, NH), dim3(32, 8)>>>(kern);
    feats_tc<<<dim3(NFP / 128, NN / 128, NH * NB), 256, G_SMEM>>>();

    // Scans need feats + sort
    cudaStreamWaitEvent(0, esort, 0);
    scan_feats<<<NH * NB * 2, 512>>>();

    // Combine needs scans + bias (+ nothing from attn slices)
    cudaStreamWaitEvent(0, eside, 0);
    combine<<<NB * NN, 256>>>(out);
}

// round 9
// speedup vs baseline: 2.2248x; 2.2248x over previous
#include <cuda_runtime.h>
#include <cuda_fp16.h>
#include <stdint.h>

#define NH 3
#define NB 16
#define NN 1024
#define NF 512
#define NFP 1024

// ---------------------------------------------------------------------------
// Scratch arena
// ---------------------------------------------------------------------------
#define OFF_XH    0ull            // x fp16            16 MB
#define OFF_KTH   16777216ull     // kernels^T fp16     3 MB
#define OFF_FTH   19922944ull     // feats^T fp16      96 MB
#define OFF_AH    120586240ull    // attn fp16         96 MB
#define OFF_W2S   221249536ull
#define OFF_W2N   221255680ull
#define OFF_SS    221261824ull
#define OFF_SN    221458432ull
#define OFF_BM    221655040ull
#define ARENA_SZ  221659136ull

__device__ __align__(128) unsigned char g_arena[ARENA_SZ];
#define AP(T, off) ((T*)(g_arena + (off)))

// ---------------------------------------------------------------------------
// PTX helpers (base sm_103 target)
// ---------------------------------------------------------------------------
__device__ __forceinline__ uint32_t smem_u32(const void* p) {
    uint32_t a;
    asm("{ .reg .u64 t; cvta.to.shared.u64 t, %1; cvt.u32.u64 %0, t; }"
        : "=r"(a) : "l"(p));
    return a;
}
__device__ __forceinline__ void cpasync16(uint32_t s, const void* g) {
    asm volatile("cp.async.cg.shared.global [%0], [%1], 16;"
                 :: "r"(s), "l"(g) : "memory");
}
__device__ __forceinline__ void cp_commit() {
    asm volatile("cp.async.commit_group;" ::: "memory");
}
template <int N>
__device__ __forceinline__ void cp_wait() {
    asm volatile("cp.async.wait_group %0;" :: "n"(N) : "memory");
}
__device__ __forceinline__ void ldsm4(uint32_t* r, uint32_t a) {
    asm volatile("ldmatrix.sync.aligned.m8n8.x4.shared.b16 {%0,%1,%2,%3}, [%4];"
                 : "=r"(r[0]), "=r"(r[1]), "=r"(r[2]), "=r"(r[3]) : "r"(a));
}
__device__ __forceinline__ void mma16816(float* c, const uint32_t* a,
                                         const uint32_t* b) {
    asm volatile(
        "mma.sync.aligned.m16n8k16.row.col.f32.f16.f16.f32 "
        "{%0,%1,%2,%3}, {%4,%5,%6,%7}, {%8,%9}, {%0,%1,%2,%3};"
        : "+f"(c[0]), "+f"(c[1]), "+f"(c[2]), "+f"(c[3])
        : "r"(a[0]), "r"(a[1]), "r"(a[2]), "r"(a[3]), "r"(b[0]), "r"(b[1]));
}

// ---------------------------------------------------------------------------
// GEMM core: 128x128 CTA tile, kc=64, fp16 K-major, 2 CTAs/SM.
// 4 warps (128 threads), warp grid 2x2, warp tile 64x64 -> acc[4][8][4].
// Per k16-step/warp: 8 LDSM : 32 HMMA (vs 6:16 before).
// 2 tiles/stage, 144B pitch, 3-stage ring, 1 sync/stage.
// ---------------------------------------------------------------------------
#define GP_PITCH  144
#define G_TILE    18432
#define G_STAGE   36864
#define G_SMEM    110592
#define G_THREADS 128

__device__ __forceinline__ void ld_stage(
    uint32_t st, int tid, const __half* A, const __half* B, int lda, int ldb)
{
#pragma unroll
    for (int it = 0; it < 8; it++) {
        const int idx = it * G_THREADS + tid;   // 0..1023
        const int row = idx >> 3, seg = idx & 7;
        const uint32_t so = row * GP_PITCH + seg * 16;
        cpasync16(st + so,          (const char*)(A + (size_t)row * lda) + seg * 16);
        cpasync16(st + G_TILE + so, (const char*)(B + (size_t)row * ldb) + seg * 16);
    }
    cp_commit();
}

// S = total kc-stages; KPH = stages per head; hst = per-head element stride.
template <int S, int KPH>
__device__ __forceinline__ void gemm_mma(
    const __half* A0, const __half* B0, size_t hst, int lda, int ldb,
    uint32_t sb, float acc[4][8][4], int wm, int wn, int lane, int tid)
{
#pragma unroll
    for (int mt = 0; mt < 4; mt++)
#pragma unroll
        for (int nt = 0; nt < 8; nt++)
#pragma unroll
            for (int q = 0; q < 4; q++) acc[mt][nt][q] = 0.f;

    ld_stage(sb,           tid, A0,      B0,      lda, ldb);
    ld_stage(sb + G_STAGE, tid, A0 + 64, B0 + 64, lda, ldb);

    for (int s = 0; s < S; s++) {
        if (s < S - 1) cp_wait<1>(); else cp_wait<0>();
        __syncthreads();
        const int sn = s + 2;
        if (sn < S) {
            const int hh = sn / KPH, kt = (sn % KPH) * 64;
            ld_stage(sb + (sn % 3) * G_STAGE, tid,
                     A0 + hh * hst + kt, B0 + hh * hst + kt, lda, ldb);
        }
        const uint32_t bu = sb + (s % 3) * G_STAGE;
        const uint32_t Ab = bu, Bb = bu + G_TILE;
#pragma unroll
        for (int ks = 0; ks < 4; ks++) {
            // B: 4 paired ldmatrix.x4, each serving two n-tiles' {k0,k8} frags.
            uint32_t bq[8][2];
            const int bcol = ks * 16 + (((lane >> 3) & 1) << 3);
            const int brow_in = ((lane >> 4) << 3) + (lane & 7);
#pragma unroll
            for (int p = 0; p < 4; p++) {
                uint32_t r[4];
                const int brow = wn * 64 + p * 16 + brow_in;
                ldsm4(r, Bb + (uint32_t)brow * GP_PITCH + bcol * 2);
                bq[2 * p][0] = r[0]; bq[2 * p][1] = r[1];
                bq[2 * p + 1][0] = r[2]; bq[2 * p + 1][1] = r[3];
            }
            const int arow = wm * 64 + (lane & 15);
            const int acol = ks * 16 + (lane >> 4) * 8;
#pragma unroll
            for (int mt = 0; mt < 4; mt++) {
                uint32_t aq[4];
                ldsm4(aq, Ab + (uint32_t)(arow + mt * 16) * GP_PITCH + acol * 2);
#pragma unroll
                for (int nt = 0; nt < 8; nt++)
                    mma16816(acc[mt][nt], aq, bq[nt]);
            }
        }
    }
}

// ---------------------------------------------------------------------------
// feats GEMM (transposed output): D[fp][node] = sum_f kT[fp][f] * x[node][f]
// M = fp (128-tile), N = node (128-tile). Output [hb][fp][node], node-major.
// ---------------------------------------------------------------------------
__global__ void __launch_bounds__(G_THREADS, 2) feats_tc() {
    extern __shared__ char dynsm[];
    const int tid = threadIdx.x;
    const int w = tid >> 5, lane = tid & 31;
    const int wm = w >> 1, wn = w & 1;
    const int z = blockIdx.z, h = z >> 4, b = z & 15;
    const int m0 = blockIdx.y * 128;   // fp tile
    const int n0 = blockIdx.x * 128;   // node tile

    const __half* A0 = AP(__half, OFF_KTH) + (size_t)h * NFP * NF + (size_t)m0 * NF;
    const __half* B0 = AP(__half, OFF_XH)  + (size_t)b * NN * NF + (size_t)n0 * NF;

    float acc[4][8][4];
    gemm_mma<8, 8>(A0, B0, 0, NF, NF, smem_u32(dynsm), acc, wm, wn, lane, tid);

    __half* ft = AP(__half, OFF_FTH) + (size_t)z * NFP * NN;
#pragma unroll
    for (int mt = 0; mt < 4; mt++)
#pragma unroll
        for (int nt = 0; nt < 8; nt++)
#pragma unroll
            for (int hf = 0; hf < 2; hf++) {
                const int row = m0 + wm * 64 + mt * 16 + (lane >> 2) + hf * 8;
                const int col = n0 + wn * 64 + nt * 8 + (lane & 3) * 2;
                __half2 p;
                p.x = __float2half(acc[mt][nt][hf * 2 + 0]);
                p.y = __float2half(acc[mt][nt][hf * 2 + 1]);
                *(__half2*)(ft + (size_t)row * NN + col) = p;
            }
}

// ---------------------------------------------------------------------------
// out GEMM: D[node][fp] = sum_h sum_j attn[h,b,node,j] * fT[h,b][fp][j]
// ---------------------------------------------------------------------------
__global__ void __launch_bounds__(G_THREADS, 2) out_tc(float* __restrict__ out) {
    extern __shared__ char dynsm[];
    const int tid = threadIdx.x;
    const int w = tid >> 5, lane = tid & 31;
    const int wm = w >> 1, wn = w & 1;
    const int b = blockIdx.z;
    const int m0 = blockIdx.y * 128;   // node tile
    const int n0 = blockIdx.x * 128;   // fp tile

    const size_t hst = (size_t)NB * NN * NN;
    const __half* A0 = AP(__half, OFF_AH)  + ((size_t)b * NN + m0) * NN;
    const __half* B0 = AP(__half, OFF_FTH) + ((size_t)b * NFP + n0) * NN;

    float acc[4][8][4];
    gemm_mma<48, 16>(A0, B0, hst, NN, NN, smem_u32(dynsm), acc, wm, wn, lane, tid);

    const float* bm = AP(float, OFF_BM);
    float* C = out + ((size_t)(NH * NB) + b) * NN * NN;
#pragma unroll
    for (int mt = 0; mt < 4; mt++)
#pragma unroll
        for (int nt = 0; nt < 8; nt++)
#pragma unroll
            for (int hf = 0; hf < 2; hf++) {
                const int row = m0 + wm * 64 + mt * 16 + (lane >> 2) + hf * 8;
                const int col = n0 + wn * 64 + nt * 8 + (lane & 3) * 2;
                float2 v;
                v.x = acc[mt][nt][hf * 2 + 0] * (1.f / 3.f) + bm[col + 0];
                v.y = acc[mt][nt][hf * 2 + 1] * (1.f / 3.f) + bm[col + 1];
                *(float2*)(C + (size_t)row * NN + col) = v;
            }
}

// ---------------------------------------------------------------------------
// Prep kernels
// ---------------------------------------------------------------------------
__global__ void prep_x(const float* __restrict__ x) {
    const size_t i = (size_t)blockIdx.x * 256 + threadIdx.x;  // NB*NN*NF/4
    float4 v = ((const float4*)x)[i];
    union { __half h[4]; uint2 u; } o;
    o.h[0] = __float2half(v.x); o.h[1] = __float2half(v.y);
    o.h[2] = __float2half(v.z); o.h[3] = __float2half(v.w);
    ((uint2*)AP(unsigned char, OFF_XH))[i] = o.u;
}

// kernels (H, F, F_) -> kT (H, F_, F) fp16
__global__ void prep_kT(const float* __restrict__ kern) {
    __shared__ float t[32][33];
    const int h = blockIdx.z;
    const int fp0 = blockIdx.x * 32, f0 = blockIdx.y * 32;
    const float* src = kern + (size_t)h * NF * NFP;
#pragma unroll
    for (int j = 0; j < 4; j++)
        t[threadIdx.y + j * 8][threadIdx.x] =
            src[(size_t)(f0 + threadIdx.y + j * 8) * NFP + fp0 + threadIdx.x];
    __syncthreads();
    __half* dst = AP(__half, OFF_KTH) + (size_t)h * NFP * NF;
#pragma unroll
    for (int j = 0; j < 4; j++) {
        float v = t[threadIdx.x][threadIdx.y + j * 8];
        dst[(size_t)(fp0 + threadIdx.y + j * 8) * NF + f0 + threadIdx.x] =
            __float2half(v);
    }
}

// w2[h][f] = sum_fp kernels[h][f][fp] * a[h][fp]
__global__ void w2k(const float* __restrict__ kern,
                    const float* __restrict__ as, const float* __restrict__ an) {
    const int gw = blockIdx.x * 8 + (threadIdx.x >> 5);
    const int lane = threadIdx.x & 31;
    const int h = gw >> 9, f = gw & 511;
    const float* row = kern + ((size_t)h * NF + f) * NFP;
    const float* a1 = as + (size_t)h * NFP;
    const float* a2 = an + (size_t)h * NFP;
    float s1 = 0.f, s2 = 0.f;
#pragma unroll
    for (int it = 0; it < 8; it++) {
        int k = it * 128 + lane * 4;
        float4 kv = *(const float4*)(row + k);
        float4 v1 = *(const float4*)(a1 + k);
        float4 v2 = *(const float4*)(a2 + k);
        s1 += kv.x * v1.x + kv.y * v1.y + kv.z * v1.z + kv.w * v1.w;
        s2 += kv.x * v2.x + kv.y * v2.y + kv.z * v2.z + kv.w * v2.w;
    }
#pragma unroll
    for (int o = 16; o > 0; o >>= 1) {
        s1 += __shfl_xor_sync(0xFFFFFFFFu, s1, o);
        s2 += __shfl_xor_sync(0xFFFFFFFFu, s2, o);
    }
    if (lane == 0) {
        AP(float, OFF_W2S)[(size_t)h * NF + f] = s1;
        AP(float, OFF_W2N)[(size_t)h * NF + f] = s2;
    }
}

// s_self[h,b,n] = x[b,n,:] . w2s[h]; s_neigh likewise
__global__ void __launch_bounds__(256) s_comp(const float* __restrict__ x) {
    __shared__ float ws[NH * NF], wn_[NH * NF];
    for (int i = threadIdx.x; i < NH * NF; i += 256) {
        ws[i]  = AP(float, OFF_W2S)[i];
        wn_[i] = AP(float, OFF_W2N)[i];
    }
    __syncthreads();
    const int gw = blockIdx.x * 8 + (threadIdx.x >> 5);
    const int lane = threadIdx.x & 31;
    const int b = gw >> 10, n = gw & 1023;
    const float* xr = x + ((size_t)b * NN + n) * NF;
    float a[3] = {0.f, 0.f, 0.f}, c[3] = {0.f, 0.f, 0.f};
#pragma unroll
    for (int it = 0; it < 4; it++) {
        int f = it * 128 + lane * 4;
        float4 xv = *(const float4*)(xr + f);
#pragma unroll
        for (int h = 0; h < 3; h++) {
            float4 w = *(const float4*)&ws[h * NF + f];
            float4 u = *(const float4*)&wn_[h * NF + f];
            a[h] += xv.x * w.x + xv.y * w.y + xv.z * w.z + xv.w * w.w;
            c[h] += xv.x * u.x + xv.y * u.y + xv.z * u.z + xv.w * u.w;
        }
    }
#pragma unroll
    for (int h = 0; h < 3; h++) {
#pragma unroll
        for (int o = 16; o > 0; o >>= 1) {
            a[h] += __shfl_xor_sync(0xFFFFFFFFu, a[h], o);
            c[h] += __shfl_xor_sync(0xFFFFFFFFu, c[h], o);
        }
    }
    if (lane == 0) {
#pragma unroll
        for (int h = 0; h < 3; h++) {
            AP(float, OFF_SS)[(size_t)h * NB * NN + b * NN + n] = a[h];
            AP(float, OFF_SN)[(size_t)h * NB * NN + b * NN + n] = c[h];
        }
    }
}

// Row softmax of leaky(s_self[i]+s_neigh[j]); fp32 attn to d_out + fp16 copy.
__global__ void __launch_bounds__(256) attn_softmax(float* __restrict__ out) {
    __shared__ float c[NN];
    const int w    = threadIdx.x >> 5;
    const int lane = threadIdx.x & 31;
    const size_t r0 = (size_t)blockIdx.x * 8;
    const size_t hb = r0 >> 10;
    const float* cn = AP(float, OFF_SN) + hb * NN;
    for (int i = threadIdx.x; i < NN; i += 256) c[i] = cn[i];
    __syncthreads();

    const size_t r = r0 + w;
    const float a = AP(float, OFF_SS)[r];

    float ev[32];
    float m = -1e30f;
#pragma unroll
    for (int it = 0; it < 32; it++) {
        float t = a + c[it * 32 + lane];
        t = (t >= 0.f) ? t : 0.2f * t;
        ev[it] = t;
        m = fmaxf(m, t);
    }
#pragma unroll
    for (int o = 16; o > 0; o >>= 1) m = fmaxf(m, __shfl_xor_sync(0xFFFFFFFFu, m, o));
    float s = 0.f;
#pragma unroll
    for (int it = 0; it < 32; it++) {
        float e = __expf(ev[it] - m);
        ev[it] = e;
        s += e;
    }
#pragma unroll
    for (int o = 16; o > 0; o >>= 1) s += __shfl_xor_sync(0xFFFFFFFFu, s, o);
    const float inv = 1.f / s;

    float* orow = out + r * NN;
    __half* ah = AP(__half, OFF_AH) + r * NN;
#pragma unroll
    for (int it = 0; it < 32; it++) {
        float v = ev[it] * inv;
        int col = it * 32 + lane;
        orow[col] = v;
        ah[col] = __float2half(v);
    }
}

__global__ void bias_mean(const float* __restrict__ biases) {
    int k = blockIdx.x * 256 + threadIdx.x;
    AP(float, OFF_BM)[k] =
        (biases[k] + biases[NFP + k] + biases[2 * NFP + k]) * (1.f / 3.f);
}

// ---------------------------------------------------------------------------
// Launch: side stream hides the scalar chain under prep + feats GEMM.
// ---------------------------------------------------------------------------
extern "C" void kernel_launch(void* const* d_in, const int* in_sizes, int n_in,
                              void* d_out, int out_size)
{
    const float* x      = (const float*)d_in[0];
    const float* kern   = (const float*)d_in[1];
    const float* biases = (const float*)d_in[2];
    const float* aself  = (const float*)d_in[3];
    const float* aneigh = (const float*)d_in[4];
    float* out = (float*)d_out;

    static cudaStream_t s1 = nullptr;
    static cudaEvent_t efork = nullptr, ejoin = nullptr;
    static bool attr_done = false;
    if (s1 == nullptr) {
        cudaStreamCreateWithFlags(&s1, cudaStreamNonBlocking);
        cudaEventCreateWithFlags(&efork, cudaEventDisableTiming);
        cudaEventCreateWithFlags(&ejoin, cudaEventDisableTiming);
    }
    if (!attr_done) {
        cudaFuncSetAttribute(feats_tc, cudaFuncAttributeMaxDynamicSharedMemorySize, G_SMEM);
        cudaFuncSetAttribute(out_tc,   cudaFuncAttributeMaxDynamicSharedMemorySize, G_SMEM);
        attr_done = true;
    }

    // Fork
    cudaEventRecord(efork, 0);
    cudaStreamWaitEvent(s1, efork, 0);

    // Branch B (side stream): logits chain + bias mean
    w2k<<<(NH * NF) / 8, 256, 0, s1>>>(kern, aself, aneigh);
    s_comp<<<(NB * NN) / 8, 256, 0, s1>>>(x);
    attn_softmax<<<(NH * NB * NN) / 8, 256, 0, s1>>>(out);
    bias_mean<<<NFP / 256, 256, 0, s1>>>(biases);

    // Branch A (main stream): fp16 prep + feats GEMM
    prep_x<<<(NB * NN * NF / 4) / 256, 256>>>(x);
    prep_kT<<<dim3(NFP / 32, NF / 32, NH), dim3(32, 8)>>>(kern);
    feats_tc<<<dim3(NN / 128, NFP / 128, NH * NB), G_THREADS, G_SMEM>>>();

    // Join, then the output GEMM (needs both branches)
    cudaEventRecord(ejoin, s1);
    cudaStreamWaitEvent(0, ejoin, 0);
    out_tc<<<dim3(NFP / 128, NN / 128, NB), G_THREADS, G_SMEM>>>(out);
}

// round 10
// speedup vs baseline: 3.0932x; 1.3903x over previous
#include <cuda_runtime.h>
#include <cuda_fp16.h>
#include <stdint.h>

#define NH 3
#define NB 16
#define NN 1024
#define NF 512
#define NFP 1024

// ---------------------------------------------------------------------------
// Scratch arena
// ---------------------------------------------------------------------------
#define OFF_XT    0ull            // x^T fp16 [b][f][n]        16 MB
#define OFF_KTH   16777216ull     // kernels^T fp16 [h][fp][f]  3 MB
#define OFF_Y     19922944ull     // y fp16 [hb][n][f]         48 MB
#define OFF_AH    70254592ull     // attn fp16 [hb][n][j]      96 MB
#define OFF_W2S   170917888ull
#define OFF_W2N   170924032ull
#define OFF_SS    170930176ull
#define OFF_SN    171126784ull
#define OFF_BM    171323392ull
#define ARENA_SZ  171327488ull

__device__ __align__(128) unsigned char g_arena[ARENA_SZ];
#define AP(T, off) ((T*)(g_arena + (off)))

// ---------------------------------------------------------------------------
// PTX helpers (base sm_103 target)
// ---------------------------------------------------------------------------
__device__ __forceinline__ uint32_t smem_u32(const void* p) {
    uint32_t a;
    asm("{ .reg .u64 t; cvta.to.shared.u64 t, %1; cvt.u32.u64 %0, t; }"
        : "=r"(a) : "l"(p));
    return a;
}
__device__ __forceinline__ void cpasync16(uint32_t s, const void* g) {
    asm volatile("cp.async.cg.shared.global [%0], [%1], 16;"
                 :: "r"(s), "l"(g) : "memory");
}
__device__ __forceinline__ void cp_commit() {
    asm volatile("cp.async.commit_group;" ::: "memory");
}
template <int N>
__device__ __forceinline__ void cp_wait() {
    asm volatile("cp.async.wait_group %0;" :: "n"(N) : "memory");
}
__device__ __forceinline__ void ldsm4(uint32_t* r, uint32_t a) {
    asm volatile("ldmatrix.sync.aligned.m8n8.x4.shared.b16 {%0,%1,%2,%3}, [%4];"
                 : "=r"(r[0]), "=r"(r[1]), "=r"(r[2]), "=r"(r[3]) : "r"(a));
}
__device__ __forceinline__ void mma16816(float* c, const uint32_t* a,
                                         const uint32_t* b) {
    asm volatile(
        "mma.sync.aligned.m16n8k16.row.col.f32.f16.f16.f32 "
        "{%0,%1,%2,%3}, {%4,%5,%6,%7}, {%8,%9}, {%0,%1,%2,%3};"
        : "+f"(c[0]), "+f"(c[1]), "+f"(c[2]), "+f"(c[3])
        : "r"(a[0]), "r"(a[1]), "r"(a[2]), "r"(a[3]), "r"(b[0]), "r"(b[1]));
}

// ---------------------------------------------------------------------------
// GEMM core (R5 config, proven): 128x128 CTA tile, kc=64, fp16 K-major.
// 256 threads, warp tile 64x32 (2x4 grid), 2 tiles/stage, 144B pitch,
// 3-stage ring, 1 sync/stage, 2 CTAs/SM. Separate head strides for A/B.
// ---------------------------------------------------------------------------
#define GP_PITCH  144
#define G_TILE    18432
#define G_STAGE   36864
#define G_SMEM    110592

__device__ __forceinline__ void ld_stage(
    uint32_t st, int tid, const __half* A, const __half* B, int lda, int ldb)
{
#pragma unroll
    for (int it = 0; it < 4; it++) {
        const int idx = it * 256 + tid;
        const int row = idx >> 3, seg = idx & 7;
        const uint32_t so = row * GP_PITCH + seg * 16;
        cpasync16(st + so,          (const char*)(A + (size_t)row * lda) + seg * 16);
        cpasync16(st + G_TILE + so, (const char*)(B + (size_t)row * ldb) + seg * 16);
    }
    cp_commit();
}

// S = total kc-stages; KPH = stages per head; hstA/hstB = per-head strides.
template <int S, int KPH>
__device__ __forceinline__ void gemm_mma(
    const __half* A0, const __half* B0, size_t hstA, size_t hstB,
    int lda, int ldb, uint32_t sb, float acc[4][4][4],
    int wm, int wn, int lane, int tid)
{
#pragma unroll
    for (int mt = 0; mt < 4; mt++)
#pragma unroll
        for (int nt = 0; nt < 4; nt++)
#pragma unroll
            for (int q = 0; q < 4; q++) acc[mt][nt][q] = 0.f;

    ld_stage(sb,           tid, A0,      B0,      lda, ldb);
    ld_stage(sb + G_STAGE, tid, A0 + 64, B0 + 64, lda, ldb);

    for (int s = 0; s < S; s++) {
        if (s < S - 1) cp_wait<1>(); else cp_wait<0>();
        __syncthreads();
        const int sn = s + 2;
        if (sn < S) {
            const int hh = sn / KPH, kt = (sn % KPH) * 64;
            ld_stage(sb + (sn % 3) * G_STAGE, tid,
                     A0 + hh * hstA + kt, B0 + hh * hstB + kt, lda, ldb);
        }
        const uint32_t bu = sb + (s % 3) * G_STAGE;
        const uint32_t Ab = bu, Bb = bu + G_TILE;
#pragma unroll
        for (int ks = 0; ks < 4; ks++) {
            uint32_t bq[4][2];
            const int bcol = ks * 16 + (((lane >> 3) & 1) << 3);
            const int brow_in = ((lane >> 4) << 3) + (lane & 7);
#pragma unroll
            for (int p = 0; p < 2; p++) {
                uint32_t r[4];
                const int brow = wn * 32 + p * 16 + brow_in;
                ldsm4(r, Bb + (uint32_t)brow * GP_PITCH + bcol * 2);
                bq[2 * p][0] = r[0]; bq[2 * p][1] = r[1];
                bq[2 * p + 1][0] = r[2]; bq[2 * p + 1][1] = r[3];
            }
            const int arow = wm * 64 + (lane & 15);
            const int acol = ks * 16 + (lane >> 4) * 8;
#pragma unroll
            for (int mt = 0; mt < 4; mt++) {
                uint32_t aq[4];
                ldsm4(aq, Ab + (uint32_t)(arow + mt * 16) * GP_PITCH + acol * 2);
#pragma unroll
                for (int nt = 0; nt < 4; nt++)
                    mma16816(acc[mt][nt], aq, bq[nt]);
            }
        }
    }
}

// ---------------------------------------------------------------------------
// G1: y[hb][node][f] = sum_j attn[hb][node][j] * xT[b][f][j]
// M = node (8 tiles), N = f (4 tiles), K = 1024.
// ---------------------------------------------------------------------------
__global__ void __launch_bounds__(256, 2) g1_tc() {
    extern __shared__ char dynsm[];
    const int tid = threadIdx.x;
    const int w = tid >> 5, lane = tid & 31;
    const int wm = w & 1, wn = w >> 1;
    const int z = blockIdx.z, b = z & 15;
    const int m0 = blockIdx.y * 128;   // node tile
    const int n0 = blockIdx.x * 128;   // f tile

    const __half* A0 = AP(__half, OFF_AH) + ((size_t)z * NN + m0) * NN;
    const __half* B0 = AP(__half, OFF_XT) + (size_t)b * NF * NN + (size_t)n0 * NN;

    float acc[4][4][4];
    gemm_mma<16, 16>(A0, B0, 0, 0, NN, NN, smem_u32(dynsm), acc, wm, wn, lane, tid);

    __half* y = AP(__half, OFF_Y) + (size_t)z * NN * NF;
#pragma unroll
    for (int mt = 0; mt < 4; mt++)
#pragma unroll
        for (int nt = 0; nt < 4; nt++)
#pragma unroll
            for (int hf = 0; hf < 2; hf++) {
                const int row = m0 + wm * 64 + mt * 16 + (lane >> 2) + hf * 8;
                const int col = n0 + wn * 32 + nt * 8 + (lane & 3) * 2;
                __half2 p;
                p.x = __float2half(acc[mt][nt][hf * 2 + 0]);
                p.y = __float2half(acc[mt][nt][hf * 2 + 1]);
                *(__half2*)(y + (size_t)row * NF + col) = p;
            }
}

// ---------------------------------------------------------------------------
// G2: out[b][node][fp] = (1/3) sum_h sum_f y[hb][node][f] * kT[h][fp][f] + bm
// M = node (8 tiles), N = fp (8 tiles), K = 3 x 512.
// ---------------------------------------------------------------------------
__global__ void __launch_bounds__(256, 2) g2_tc(float* __restrict__ out) {
    extern __shared__ char dynsm[];
    const int tid = threadIdx.x;
    const int w = tid >> 5, lane = tid & 31;
    const int wm = w & 1, wn = w >> 1;
    const int b = blockIdx.z;
    const int m0 = blockIdx.y * 128;   // node tile
    const int n0 = blockIdx.x * 128;   // fp tile

    const size_t hstA = (size_t)NB * NN * NF;   // head stride in y (hb = h*NB+b)
    const size_t hstB = (size_t)NFP * NF;       // head stride in kT
    const __half* A0 = AP(__half, OFF_Y)   + ((size_t)b * NN + m0) * NF;
    const __half* B0 = AP(__half, OFF_KTH) + (size_t)n0 * NF;

    float acc[4][4][4];
    gemm_mma<24, 8>(A0, B0, hstA, hstB, NF, NF, smem_u32(dynsm), acc, wm, wn, lane, tid);

    const float* bm = AP(float, OFF_BM);
    float* C = out + ((size_t)(NH * NB) + b) * NN * NN;
#pragma unroll
    for (int mt = 0; mt < 4; mt++)
#pragma unroll
        for (int nt = 0; nt < 4; nt++)
#pragma unroll
            for (int hf = 0; hf < 2; hf++) {
                const int row = m0 + wm * 64 + mt * 16 + (lane >> 2) + hf * 8;
                const int col = n0 + wn * 32 + nt * 8 + (lane & 3) * 2;
                float2 v;
                v.x = acc[mt][nt][hf * 2 + 0] * (1.f / 3.f) + bm[col + 0];
                v.y = acc[mt][nt][hf * 2 + 1] * (1.f / 3.f) + bm[col + 1];
                *(float2*)(C + (size_t)row * NN + col) = v;
            }
}

// ---------------------------------------------------------------------------
// Prep kernels
// ---------------------------------------------------------------------------
// x (b, n, f) fp32 -> xT (b, f, n) fp16
__global__ void prep_xT(const float* __restrict__ x) {
    __shared__ float t[32][33];
    const int b = blockIdx.z;
    const int n0 = blockIdx.x * 32, f0 = blockIdx.y * 32;
    const float* src = x + (size_t)b * NN * NF;
#pragma unroll
    for (int j = 0; j < 4; j++)
        t[threadIdx.y + j * 8][threadIdx.x] =
            src[(size_t)(n0 + threadIdx.y + j * 8) * NF + f0 + threadIdx.x];
    __syncthreads();
    __half* dst = AP(__half, OFF_XT) + (size_t)b * NF * NN;
#pragma unroll
    for (int j = 0; j < 4; j++) {
        float v = t[threadIdx.x][threadIdx.y + j * 8];
        dst[(size_t)(f0 + threadIdx.y + j * 8) * NN + n0 + threadIdx.x] =
            __float2half(v);
    }
}

// kernels (H, F, F_) -> kT (H, F_, F) fp16
__global__ void prep_kT(const float* __restrict__ kern) {
    __shared__ float t[32][33];
    const int h = blockIdx.z;
    const int fp0 = blockIdx.x * 32, f0 = blockIdx.y * 32;
    const float* src = kern + (size_t)h * NF * NFP;
#pragma unroll
    for (int j = 0; j < 4; j++)
        t[threadIdx.y + j * 8][threadIdx.x] =
            src[(size_t)(f0 + threadIdx.y + j * 8) * NFP + fp0 + threadIdx.x];
    __syncthreads();
    __half* dst = AP(__half, OFF_KTH) + (size_t)h * NFP * NF;
#pragma unroll
    for (int j = 0; j < 4; j++) {
        float v = t[threadIdx.x][threadIdx.y + j * 8];
        dst[(size_t)(fp0 + threadIdx.y + j * 8) * NF + f0 + threadIdx.x] =
            __float2half(v);
    }
}

// w2[h][f] = sum_fp kernels[h][f][fp] * a[h][fp]
__global__ void w2k(const float* __restrict__ kern,
                    const float* __restrict__ as, const float* __restrict__ an) {
    const int gw = blockIdx.x * 8 + (threadIdx.x >> 5);
    const int lane = threadIdx.x & 31;
    const int h = gw >> 9, f = gw & 511;
    const float* row = kern + ((size_t)h * NF + f) * NFP;
    const float* a1 = as + (size_t)h * NFP;
    const float* a2 = an + (size_t)h * NFP;
    float s1 = 0.f, s2 = 0.f;
#pragma unroll
    for (int it = 0; it < 8; it++) {
        int k = it * 128 + lane * 4;
        float4 kv = *(const float4*)(row + k);
        float4 v1 = *(const float4*)(a1 + k);
        float4 v2 = *(const float4*)(a2 + k);
        s1 += kv.x * v1.x + kv.y * v1.y + kv.z * v1.z + kv.w * v1.w;
        s2 += kv.x * v2.x + kv.y * v2.y + kv.z * v2.z + kv.w * v2.w;
    }
#pragma unroll
    for (int o = 16; o > 0; o >>= 1) {
        s1 += __shfl_xor_sync(0xFFFFFFFFu, s1, o);
        s2 += __shfl_xor_sync(0xFFFFFFFFu, s2, o);
    }
    if (lane == 0) {
        AP(float, OFF_W2S)[(size_t)h * NF + f] = s1;
        AP(float, OFF_W2N)[(size_t)h * NF + f] = s2;
    }
}

// s_self[h,b,n] = x[b,n,:] . w2s[h]; s_neigh likewise
__global__ void __launch_bounds__(256) s_comp(const float* __restrict__ x) {
    __shared__ float ws[NH * NF], wn_[NH * NF];
    for (int i = threadIdx.x; i < NH * NF; i += 256) {
        ws[i]  = AP(float, OFF_W2S)[i];
        wn_[i] = AP(float, OFF_W2N)[i];
    }
    __syncthreads();
    const int gw = blockIdx.x * 8 + (threadIdx.x >> 5);
    const int lane = threadIdx.x & 31;
    const int b = gw >> 10, n = gw & 1023;
    const float* xr = x + ((size_t)b * NN + n) * NF;
    float a[3] = {0.f, 0.f, 0.f}, c[3] = {0.f, 0.f, 0.f};
#pragma unroll
    for (int it = 0; it < 4; it++) {
        int f = it * 128 + lane * 4;
        float4 xv = *(const float4*)(xr + f);
#pragma unroll
        for (int h = 0; h < 3; h++) {
            float4 w = *(const float4*)&ws[h * NF + f];
            float4 u = *(const float4*)&wn_[h * NF + f];
            a[h] += xv.x * w.x + xv.y * w.y + xv.z * w.z + xv.w * w.w;
            c[h] += xv.x * u.x + xv.y * u.y + xv.z * u.z + xv.w * u.w;
        }
    }
#pragma unroll
    for (int h = 0; h < 3; h++) {
#pragma unroll
        for (int o = 16; o > 0; o >>= 1) {
            a[h] += __shfl_xor_sync(0xFFFFFFFFu, a[h], o);
            c[h] += __shfl_xor_sync(0xFFFFFFFFu, c[h], o);
        }
    }
    if (lane == 0) {
#pragma unroll
        for (int h = 0; h < 3; h++) {
            AP(float, OFF_SS)[(size_t)h * NB * NN + b * NN + n] = a[h];
            AP(float, OFF_SN)[(size_t)h * NB * NN + b * NN + n] = c[h];
        }
    }
}

// Row softmax of leaky(s_self[i]+s_neigh[j]); fp32 attn to d_out + fp16 copy.
__global__ void __launch_bounds__(256) attn_softmax(float* __restrict__ out) {
    __shared__ float c[NN];
    const int w    = threadIdx.x >> 5;
    const int lane = threadIdx.x & 31;
    const size_t r0 = (size_t)blockIdx.x * 8;
    const size_t hb = r0 >> 10;
    const float* cn = AP(float, OFF_SN) + hb * NN;
    for (int i = threadIdx.x; i < NN; i += 256) c[i] = cn[i];
    __syncthreads();

    const size_t r = r0 + w;
    const float a = AP(float, OFF_SS)[r];

    float ev[32];
    float m = -1e30f;
#pragma unroll
    for (int it = 0; it < 32; it++) {
        float t = a + c[it * 32 + lane];
        t = (t >= 0.f) ? t : 0.2f * t;
        ev[it] = t;
        m = fmaxf(m, t);
    }
#pragma unroll
    for (int o = 16; o > 0; o >>= 1) m = fmaxf(m, __shfl_xor_sync(0xFFFFFFFFu, m, o));
    float s = 0.f;
#pragma unroll
    for (int it = 0; it < 32; it++) {
        float e = __expf(ev[it] - m);
        ev[it] = e;
        s += e;
    }
#pragma unroll
    for (int o = 16; o > 0; o >>= 1) s += __shfl_xor_sync(0xFFFFFFFFu, s, o);
    const float inv = 1.f / s;

    float* orow = out + r * NN;
    __half* ah = AP(__half, OFF_AH) + r * NN;
#pragma unroll
    for (int it = 0; it < 32; it++) {
        float v = ev[it] * inv;
        int col = it * 32 + lane;
        orow[col] = v;
        ah[col] = __float2half(v);
    }
}

__global__ void bias_mean(const float* __restrict__ biases) {
    int k = blockIdx.x * 256 + threadIdx.x;
    AP(float, OFF_BM)[k] =
        (biases[k] + biases[NFP + k] + biases[2 * NFP + k]) * (1.f / 3.f);
}

// ---------------------------------------------------------------------------
// Launch: side stream runs the attn chain while the main stream preps
// transposed fp16 operands; join before G1 -> G2.
// ---------------------------------------------------------------------------
extern "C" void kernel_launch(void* const* d_in, const int* in_sizes, int n_in,
                              void* d_out, int out_size)
{
    const float* x      = (const float*)d_in[0];
    const float* kern   = (const float*)d_in[1];
    const float* biases = (const float*)d_in[2];
    const float* aself  = (const float*)d_in[3];
    const float* aneigh = (const float*)d_in[4];
    float* out = (float*)d_out;

    static cudaStream_t s1 = nullptr;
    static cudaEvent_t efork = nullptr, ejoin = nullptr;
    static bool attr_done = false;
    if (s1 == nullptr) {
        cudaStreamCreateWithFlags(&s1, cudaStreamNonBlocking);
        cudaEventCreateWithFlags(&efork, cudaEventDisableTiming);
        cudaEventCreateWithFlags(&ejoin, cudaEventDisableTiming);
    }
    if (!attr_done) {
        cudaFuncSetAttribute(g1_tc, cudaFuncAttributeMaxDynamicSharedMemorySize, G_SMEM);
        cudaFuncSetAttribute(g2_tc, cudaFuncAttributeMaxDynamicSharedMemorySize, G_SMEM);
        attr_done = true;
    }

    // Fork
    cudaEventRecord(efork, 0);
    cudaStreamWaitEvent(s1, efork, 0);

    // Side stream: attn chain (gates G1)
    w2k<<<(NH * NF) / 8, 256, 0, s1>>>(kern, aself, aneigh);
    s_comp<<<(NB * NN) / 8, 256, 0, s1>>>(x);
    attn_softmax<<<(NH * NB * NN) / 8, 256, 0, s1>>>(out);
    cudaEventRecord(ejoin, s1);

    // Main stream: operand prep (independent of the chain)
    prep_xT<<<dim3(NN / 32, NF / 32, NB), dim3(32, 8)>>>(x);
    prep_kT<<<dim3(NFP / 32, NF / 32, NH), dim3(32, 8)>>>(kern);
    bias_mean<<<NFP / 256, 256>>>(biases);

    // G1 needs attn + xT; G2 needs y + kT + bias_mean
    cudaStreamWaitEvent(0, ejoin, 0);
    g1_tc<<<dim3(NF / 128, NN / 128, NH * NB), 256, G_SMEM>>>();
    g2_tc<<<dim3(NFP / 128, NN / 128, NB), 256, G_SMEM>>>(out);
}

// round 11
// speedup vs baseline: 3.1269x; 1.0109x over previous
#include <cuda_runtime.h>
#include <cuda_fp16.h>
#include <stdint.h>

#define NH 3
#define NB 16
#define NN 1024
#define NF 512
#define NFP 1024

// ---------------------------------------------------------------------------
// Scratch arena
// ---------------------------------------------------------------------------
#define OFF_XT    0ull            // x^T fp16 [b][f][n]        16 MB
#define OFF_KTH   16777216ull     // kernels^T fp16 [h][fp][f]  3 MB
#define OFF_Y     19922944ull     // y fp16 [hb][n][f]         48 MB
#define OFF_AH    70254592ull     // attn fp16 [hb][n][j]      96 MB
#define OFF_W2S   170917888ull
#define OFF_W2N   170924032ull
#define OFF_SS    170930176ull
#define OFF_SN    171126784ull
#define OFF_BM    171323392ull
#define ARENA_SZ  171327488ull

__device__ __align__(128) unsigned char g_arena[ARENA_SZ];
#define AP(T, off) ((T*)(g_arena + (off)))

// ---------------------------------------------------------------------------
// PTX helpers (base sm_103 target)
// ---------------------------------------------------------------------------
__device__ __forceinline__ uint32_t smem_u32(const void* p) {
    uint32_t a;
    asm("{ .reg .u64 t; cvta.to.shared.u64 t, %1; cvt.u32.u64 %0, t; }"
        : "=r"(a) : "l"(p));
    return a;
}
__device__ __forceinline__ void cpasync16(uint32_t s, const void* g) {
    asm volatile("cp.async.cg.shared.global [%0], [%1], 16;"
                 :: "r"(s), "l"(g) : "memory");
}
__device__ __forceinline__ void cp_commit() {
    asm volatile("cp.async.commit_group;" ::: "memory");
}
template <int N>
__device__ __forceinline__ void cp_wait() {
    asm volatile("cp.async.wait_group %0;" :: "n"(N) : "memory");
}
__device__ __forceinline__ void ldsm4(uint32_t* r, uint32_t a) {
    asm volatile("ldmatrix.sync.aligned.m8n8.x4.shared.b16 {%0,%1,%2,%3}, [%4];"
                 : "=r"(r[0]), "=r"(r[1]), "=r"(r[2]), "=r"(r[3]) : "r"(a));
}
__device__ __forceinline__ void mma16816(float* c, const uint32_t* a,
                                         const uint32_t* b) {
    asm volatile(
        "mma.sync.aligned.m16n8k16.row.col.f32.f16.f16.f32 "
        "{%0,%1,%2,%3}, {%4,%5,%6,%7}, {%8,%9}, {%0,%1,%2,%3};"
        : "+f"(c[0]), "+f"(c[1]), "+f"(c[2]), "+f"(c[3])
        : "r"(a[0]), "r"(a[1]), "r"(a[2]), "r"(a[3]), "r"(b[0]), "r"(b[1]));
}

// ---------------------------------------------------------------------------
// GEMM core (R5 config, proven): 128x128 CTA tile, kc=64, fp16 K-major.
// 256 threads, warp tile 64x32 (2x4 grid), 2 tiles/stage, 144B pitch,
// 3-stage ring, 1 sync/stage, 2 CTAs/SM. Separate head strides for A/B.
// ---------------------------------------------------------------------------
#define GP_PITCH  144
#define G_TILE    18432
#define G_STAGE   36864
#define G_SMEM    110592

__device__ __forceinline__ void ld_stage(
    uint32_t st, int tid, const __half* A, const __half* B, int lda, int ldb)
{
#pragma unroll
    for (int it = 0; it < 4; it++) {
        const int idx = it * 256 + tid;
        const int row = idx >> 3, seg = idx & 7;
        const uint32_t so = row * GP_PITCH + seg * 16;
        cpasync16(st + so,          (const char*)(A + (size_t)row * lda) + seg * 16);
        cpasync16(st + G_TILE + so, (const char*)(B + (size_t)row * ldb) + seg * 16);
    }
    cp_commit();
}

// S = total kc-stages; KPH = stages per head; hstA/hstB = per-head strides.
template <int S, int KPH>
__device__ __forceinline__ void gemm_mma(
    const __half* A0, const __half* B0, size_t hstA, size_t hstB,
    int lda, int ldb, uint32_t sb, float acc[4][4][4],
    int wm, int wn, int lane, int tid)
{
#pragma unroll
    for (int mt = 0; mt < 4; mt++)
#pragma unroll
        for (int nt = 0; nt < 4; nt++)
#pragma unroll
            for (int q = 0; q < 4; q++) acc[mt][nt][q] = 0.f;

    ld_stage(sb,           tid, A0,      B0,      lda, ldb);
    ld_stage(sb + G_STAGE, tid, A0 + 64, B0 + 64, lda, ldb);

    for (int s = 0; s < S; s++) {
        if (s < S - 1) cp_wait<1>(); else cp_wait<0>();
        __syncthreads();
        const int sn = s + 2;
        if (sn < S) {
            const int hh = sn / KPH, kt = (sn % KPH) * 64;
            ld_stage(sb + (sn % 3) * G_STAGE, tid,
                     A0 + hh * hstA + kt, B0 + hh * hstB + kt, lda, ldb);
        }
        const uint32_t bu = sb + (s % 3) * G_STAGE;
        const uint32_t Ab = bu, Bb = bu + G_TILE;
#pragma unroll
        for (int ks = 0; ks < 4; ks++) {
            uint32_t bq[4][2];
            const int bcol = ks * 16 + (((lane >> 3) & 1) << 3);
            const int brow_in = ((lane >> 4) << 3) + (lane & 7);
#pragma unroll
            for (int p = 0; p < 2; p++) {
                uint32_t r[4];
                const int brow = wn * 32 + p * 16 + brow_in;
                ldsm4(r, Bb + (uint32_t)brow * GP_PITCH + bcol * 2);
                bq[2 * p][0] = r[0]; bq[2 * p][1] = r[1];
                bq[2 * p + 1][0] = r[2]; bq[2 * p + 1][1] = r[3];
            }
            const int arow = wm * 64 + (lane & 15);
            const int acol = ks * 16 + (lane >> 4) * 8;
#pragma unroll
            for (int mt = 0; mt < 4; mt++) {
                uint32_t aq[4];
                ldsm4(aq, Ab + (uint32_t)(arow + mt * 16) * GP_PITCH + acol * 2);
#pragma unroll
                for (int nt = 0; nt < 4; nt++)
                    mma16816(acc[mt][nt], aq, bq[nt]);
            }
        }
    }
}

// ---------------------------------------------------------------------------
// G1 (per head h): y[hb][node][f] = sum_j attn[hb][node][j] * xT[b][f][j]
// M = node (8 tiles), N = f (4 tiles), K = 1024. grid (4, 8, 16)
// ---------------------------------------------------------------------------
__global__ void __launch_bounds__(256, 2) g1_tc(int h) {
    extern __shared__ char dynsm[];
    const int tid = threadIdx.x;
    const int w = tid >> 5, lane = tid & 31;
    const int wm = w & 1, wn = w >> 1;
    const int b = blockIdx.z;
    const int z = h * NB + b;
    const int m0 = blockIdx.y * 128;   // node tile
    const int n0 = blockIdx.x * 128;   // f tile

    const __half* A0 = AP(__half, OFF_AH) + ((size_t)z * NN + m0) * NN;
    const __half* B0 = AP(__half, OFF_XT) + (size_t)b * NF * NN + (size_t)n0 * NN;

    float acc[4][4][4];
    gemm_mma<16, 16>(A0, B0, 0, 0, NN, NN, smem_u32(dynsm), acc, wm, wn, lane, tid);

    __half* y = AP(__half, OFF_Y) + (size_t)z * NN * NF;
#pragma unroll
    for (int mt = 0; mt < 4; mt++)
#pragma unroll
        for (int nt = 0; nt < 4; nt++)
#pragma unroll
            for (int hf = 0; hf < 2; hf++) {
                const int row = m0 + wm * 64 + mt * 16 + (lane >> 2) + hf * 8;
                const int col = n0 + wn * 32 + nt * 8 + (lane & 3) * 2;
                __half2 p;
                p.x = __float2half(acc[mt][nt][hf * 2 + 0]);
                p.y = __float2half(acc[mt][nt][hf * 2 + 1]);
                *(__half2*)(y + (size_t)row * NF + col) = p;
            }
}

// ---------------------------------------------------------------------------
// G2: out[b][node][fp] = (1/3) sum_h sum_f y[hb][node][f] * kT[h][fp][f] + bm
// ---------------------------------------------------------------------------
__global__ void __launch_bounds__(256, 2) g2_tc(float* __restrict__ out) {
    extern __shared__ char dynsm[];
    const int tid = threadIdx.x;
    const int w = tid >> 5, lane = tid & 31;
    const int wm = w & 1, wn = w >> 1;
    const int b = blockIdx.z;
    const int m0 = blockIdx.y * 128;   // node tile
    const int n0 = blockIdx.x * 128;   // fp tile

    const size_t hstA = (size_t)NB * NN * NF;   // head stride in y (hb = h*NB+b)
    const size_t hstB = (size_t)NFP * NF;       // head stride in kT
    const __half* A0 = AP(__half, OFF_Y)   + ((size_t)b * NN + m0) * NF;
    const __half* B0 = AP(__half, OFF_KTH) + (size_t)n0 * NF;

    float acc[4][4][4];
    gemm_mma<24, 8>(A0, B0, hstA, hstB, NF, NF, smem_u32(dynsm), acc, wm, wn, lane, tid);

    const float* bm = AP(float, OFF_BM);
    float* C = out + ((size_t)(NH * NB) + b) * NN * NN;
#pragma unroll
    for (int mt = 0; mt < 4; mt++)
#pragma unroll
        for (int nt = 0; nt < 4; nt++)
#pragma unroll
            for (int hf = 0; hf < 2; hf++) {
                const int row = m0 + wm * 64 + mt * 16 + (lane >> 2) + hf * 8;
                const int col = n0 + wn * 32 + nt * 8 + (lane & 3) * 2;
                float2 v;
                v.x = acc[mt][nt][hf * 2 + 0] * (1.f / 3.f) + bm[col + 0];
                v.y = acc[mt][nt][hf * 2 + 1] * (1.f / 3.f) + bm[col + 1];
                *(float2*)(C + (size_t)row * NN + col) = v;
            }
}

// ---------------------------------------------------------------------------
// Prep kernels
// ---------------------------------------------------------------------------
// x (b, n, f) fp32 -> xT (b, f, n) fp16
__global__ void prep_xT(const float* __restrict__ x) {
    __shared__ float t[32][33];
    const int b = blockIdx.z;
    const int n0 = blockIdx.x * 32, f0 = blockIdx.y * 32;
    const float* src = x + (size_t)b * NN * NF;
#pragma unroll
    for (int j = 0; j < 4; j++)
        t[threadIdx.y + j * 8][threadIdx.x] =
            src[(size_t)(n0 + threadIdx.y + j * 8) * NF + f0 + threadIdx.x];
    __syncthreads();
    __half* dst = AP(__half, OFF_XT) + (size_t)b * NF * NN;
#pragma unroll
    for (int j = 0; j < 4; j++) {
        float v = t[threadIdx.x][threadIdx.y + j * 8];
        dst[(size_t)(f0 + threadIdx.y + j * 8) * NN + n0 + threadIdx.x] =
            __float2half(v);
    }
}

// kernels (H, F, F_) -> kT (H, F_, F) fp16
__global__ void prep_kT(const float* __restrict__ kern) {
    __shared__ float t[32][33];
    const int h = blockIdx.z;
    const int fp0 = blockIdx.x * 32, f0 = blockIdx.y * 32;
    const float* src = kern + (size_t)h * NF * NFP;
#pragma unroll
    for (int j = 0; j < 4; j++)
        t[threadIdx.y + j * 8][threadIdx.x] =
            src[(size_t)(f0 + threadIdx.y + j * 8) * NFP + fp0 + threadIdx.x];
    __syncthreads();
    __half* dst = AP(__half, OFF_KTH) + (size_t)h * NFP * NF;
#pragma unroll
    for (int j = 0; j < 4; j++) {
        float v = t[threadIdx.x][threadIdx.y + j * 8];
        dst[(size_t)(fp0 + threadIdx.y + j * 8) * NF + f0 + threadIdx.x] =
            __float2half(v);
    }
}

// w2[h][f] = sum_fp kernels[h][f][fp] * a[h][fp]
__global__ void w2k(const float* __restrict__ kern,
                    const float* __restrict__ as, const float* __restrict__ an) {
    const int gw = blockIdx.x * 8 + (threadIdx.x >> 5);
    const int lane = threadIdx.x & 31;
    const int h = gw >> 9, f = gw & 511;
    const float* row = kern + ((size_t)h * NF + f) * NFP;
    const float* a1 = as + (size_t)h * NFP;
    const float* a2 = an + (size_t)h * NFP;
    float s1 = 0.f, s2 = 0.f;
#pragma unroll
    for (int it = 0; it < 8; it++) {
        int k = it * 128 + lane * 4;
        float4 kv = *(const float4*)(row + k);
        float4 v1 = *(const float4*)(a1 + k);
        float4 v2 = *(const float4*)(a2 + k);
        s1 += kv.x * v1.x + kv.y * v1.y + kv.z * v1.z + kv.w * v1.w;
        s2 += kv.x * v2.x + kv.y * v2.y + kv.z * v2.z + kv.w * v2.w;
    }
#pragma unroll
    for (int o = 16; o > 0; o >>= 1) {
        s1 += __shfl_xor_sync(0xFFFFFFFFu, s1, o);
        s2 += __shfl_xor_sync(0xFFFFFFFFu, s2, o);
    }
    if (lane == 0) {
        AP(float, OFF_W2S)[(size_t)h * NF + f] = s1;
        AP(float, OFF_W2N)[(size_t)h * NF + f] = s2;
    }
}

// s_self[h,b,n] = x[b,n,:] . w2s[h]; s_neigh likewise
__global__ void __launch_bounds__(256) s_comp(const float* __restrict__ x) {
    __shared__ float ws[NH * NF], wn_[NH * NF];
    for (int i = threadIdx.x; i < NH * NF; i += 256) {
        ws[i]  = AP(float, OFF_W2S)[i];
        wn_[i] = AP(float, OFF_W2N)[i];
    }
    __syncthreads();
    const int gw = blockIdx.x * 8 + (threadIdx.x >> 5);
    const int lane = threadIdx.x & 31;
    const int b = gw >> 10, n = gw & 1023;
    const float* xr = x + ((size_t)b * NN + n) * NF;
    float a[3] = {0.f, 0.f, 0.f}, c[3] = {0.f, 0.f, 0.f};
#pragma unroll
    for (int it = 0; it < 4; it++) {
        int f = it * 128 + lane * 4;
        float4 xv = *(const float4*)(xr + f);
#pragma unroll
        for (int h = 0; h < 3; h++) {
            float4 w = *(const float4*)&ws[h * NF + f];
            float4 u = *(const float4*)&wn_[h * NF + f];
            a[h] += xv.x * w.x + xv.y * w.y + xv.z * w.z + xv.w * w.w;
            c[h] += xv.x * u.x + xv.y * u.y + xv.z * u.z + xv.w * u.w;
        }
    }
#pragma unroll
    for (int h = 0; h < 3; h++) {
#pragma unroll
        for (int o = 16; o > 0; o >>= 1) {
            a[h] += __shfl_xor_sync(0xFFFFFFFFu, a[h], o);
            c[h] += __shfl_xor_sync(0xFFFFFFFFu, c[h], o);
        }
    }
    if (lane == 0) {
#pragma unroll
        for (int h = 0; h < 3; h++) {
            AP(float, OFF_SS)[(size_t)h * NB * NN + b * NN + n] = a[h];
            AP(float, OFF_SN)[(size_t)h * NB * NN + b * NN + n] = c[h];
        }
    }
}

// Per-head row softmax; fp32 attn to d_out + fp16 copy. grid 2048, h passed in.
__global__ void __launch_bounds__(256) attn_softmax(float* __restrict__ out, int h) {
    __shared__ float c[NN];
    const int w    = threadIdx.x >> 5;
    const int lane = threadIdx.x & 31;
    const size_t r0 = (size_t)h * NB * NN + (size_t)blockIdx.x * 8;
    const size_t hb = r0 >> 10;
    const float* cn = AP(float, OFF_SN) + hb * NN;
    for (int i = threadIdx.x; i < NN; i += 256) c[i] = cn[i];
    __syncthreads();

    const size_t r = r0 + w;
    const float a = AP(float, OFF_SS)[r];

    float ev[32];
    float m = -1e30f;
#pragma unroll
    for (int it = 0; it < 32; it++) {
        float t = a + c[it * 32 + lane];
        t = (t >= 0.f) ? t : 0.2f * t;
        ev[it] = t;
        m = fmaxf(m, t);
    }
#pragma unroll
    for (int o = 16; o > 0; o >>= 1) m = fmaxf(m, __shfl_xor_sync(0xFFFFFFFFu, m, o));
    float s = 0.f;
#pragma unroll
    for (int it = 0; it < 32; it++) {
        float e = __expf(ev[it] - m);
        ev[it] = e;
        s += e;
    }
#pragma unroll
    for (int o = 16; o > 0; o >>= 1) s += __shfl_xor_sync(0xFFFFFFFFu, s, o);
    const float inv = 1.f / s;

    float* orow = out + r * NN;
    __half* ah = AP(__half, OFF_AH) + r * NN;
#pragma unroll
    for (int it = 0; it < 32; it++) {
        float v = ev[it] * inv;
        int col = it * 32 + lane;
        orow[col] = v;
        ah[col] = __float2half(v);
    }
}

__global__ void bias_mean(const float* __restrict__ biases) {
    int k = blockIdx.x * 256 + threadIdx.x;
    AP(float, OFF_BM)[k] =
        (biases[k] + biases[NFP + k] + biases[2 * NFP + k]) * (1.f / 3.f);
}

// ---------------------------------------------------------------------------
// Launch DAG:
//   s1: w2k -> s_comp -> softmax(h0)[e0] -> softmax(h1)[e1] -> softmax(h2)[e2]
//   0 : prep_xT -> prep_kT -> bias_mean -> (wait e0) g1(h0)
//   s2: (wait eprep, e1) g1(h1) [eb]
//   s3: (wait eprep, e2) g1(h2) [ec]
//   0 : (wait eb, ec) g2
// ---------------------------------------------------------------------------
extern "C" void kernel_launch(void* const* d_in, const int* in_sizes, int n_in,
                              void* d_out, int out_size)
{
    const float* x      = (const float*)d_in[0];
    const float* kern   = (const float*)d_in[1];
    const float* biases = (const float*)d_in[2];
    const float* aself  = (const float*)d_in[3];
    const float* aneigh = (const float*)d_in[4];
    float* out = (float*)d_out;

    static cudaStream_t s1 = nullptr, s2 = nullptr, s3 = nullptr;
    static cudaEvent_t efork = nullptr, eprep = nullptr;
    static cudaEvent_t esm[3] = {nullptr, nullptr, nullptr};
    static cudaEvent_t eg1b = nullptr, eg1c = nullptr;
    static bool attr_done = false;
    if (s1 == nullptr) {
        cudaStreamCreateWithFlags(&s1, cudaStreamNonBlocking);
        cudaStreamCreateWithFlags(&s2, cudaStreamNonBlocking);
        cudaStreamCreateWithFlags(&s3, cudaStreamNonBlocking);
        cudaEventCreateWithFlags(&efork, cudaEventDisableTiming);
        cudaEventCreateWithFlags(&eprep, cudaEventDisableTiming);
        for (int h = 0; h < 3; h++)
            cudaEventCreateWithFlags(&esm[h], cudaEventDisableTiming);
        cudaEventCreateWithFlags(&eg1b, cudaEventDisableTiming);
        cudaEventCreateWithFlags(&eg1c, cudaEventDisableTiming);
    }
    if (!attr_done) {
        cudaFuncSetAttribute(g1_tc, cudaFuncAttributeMaxDynamicSharedMemorySize, G_SMEM);
        cudaFuncSetAttribute(g2_tc, cudaFuncAttributeMaxDynamicSharedMemorySize, G_SMEM);
        attr_done = true;
    }

    // Fork
    cudaEventRecord(efork, 0);
    cudaStreamWaitEvent(s1, efork, 0);

    // Side stream: attn chain, per-head softmax
    w2k<<<(NH * NF) / 8, 256, 0, s1>>>(kern, aself, aneigh);
    s_comp<<<(NB * NN) / 8, 256, 0, s1>>>(x);
    for (int h = 0; h < 3; h++) {
        attn_softmax<<<(NB * NN) / 8, 256, 0, s1>>>(out, h);
        cudaEventRecord(esm[h], s1);
    }

    // Main stream: operand prep
    prep_xT<<<dim3(NN / 32, NF / 32, NB), dim3(32, 8)>>>(x);
    prep_kT<<<dim3(NFP / 32, NF / 32, NH), dim3(32, 8)>>>(kern);
    bias_mean<<<NFP / 256, 256>>>(biases);
    cudaEventRecord(eprep, 0);

    // g1 per head: h0 on main, h1/h2 on s2/s3 (tails overlap)
    cudaStreamWaitEvent(0, esm[0], 0);
    g1_tc<<<dim3(NF / 128, NN / 128, NB), 256, G_SMEM>>>(0);

    cudaStreamWaitEvent(s2, eprep, 0);
    cudaStreamWaitEvent(s2, esm[1], 0);
    g1_tc<<<dim3(NF / 128, NN / 128, NB), 256, G_SMEM, s2>>>(1);
    cudaEventRecord(eg1b, s2);

    cudaStreamWaitEvent(s3, eprep, 0);
    cudaStreamWaitEvent(s3, esm[2], 0);
    g1_tc<<<dim3(NF / 128, NN / 128, NB), 256, G_SMEM, s3>>>(2);
    cudaEventRecord(eg1c, s3);

    // g2 after all of g1
    cudaStreamWaitEvent(0, eg1b, 0);
    cudaStreamWaitEvent(0, eg1c, 0);
    g2_tc<<<dim3(NFP / 128, NN / 128, NB), 256, G_SMEM>>>(out);
}